// round 16
// baseline (speedup 1.0000x reference)
#include <cuda_runtime.h>
#include <cuda_bf16.h>
#include <cstdint>

#define N_NODES 100000
#define N_EDGES 400000
#define N_GRAPHS 256
#define HID 256
#define LAYERS 3
#define EPSN 1e-5f

// ---------------- scratch (device globals; no allocations) ----------------
__device__ float g_h[N_NODES * HID];
__device__ float g_e[N_EDGES * HID];
__device__ float g_z[N_NODES * HID];
__device__ float g_t[N_NODES * HID];
__device__ float g_gsum[N_GRAPHS * HID];
__device__ float g_gsq[N_GRAPHS * HID];
__device__ float g_cnt[N_GRAPHS];
__device__ float g_M4[4 * HID];
__device__ float g_c[HID];
__device__ float g_cvec[HID];
// CSR-by-dst
__device__ int g_deg[N_NODES];
__device__ int g_cur[N_NODES];
__device__ int g_rowptr[N_NODES];
__device__ int g_perm[N_EDGES];

// ---------------- PTX helpers ----------------
__device__ __forceinline__ uint32_t smem_to_u32(const void* p) {
    uint32_t a;
    asm("{ .reg .u64 t; cvta.to.shared.u64 t, %1; cvt.u32.u64 %0, t; }" : "=r"(a) : "l"(p));
    return a;
}
__device__ __forceinline__ void cp_async16(uint32_t dst, const void* src, int src_bytes) {
    asm volatile("cp.async.ca.shared.global [%0], [%1], 16, %2;"
                 :: "r"(dst), "l"(src), "r"(src_bytes));
}
#define CP_COMMIT() asm volatile("cp.async.commit_group;" ::: "memory")
#define CP_WAIT3() asm volatile("cp.async.wait_group 3;" ::: "memory")
#define CP_WAIT0() asm volatile("cp.async.wait_group 0;" ::: "memory")

// ---------------- small helpers ----------------
__global__ void k_zero_cnt() {
    int i = threadIdx.x;
    if (i < N_GRAPHS) g_cnt[i] = 0.f;
}
__global__ void k_count(const int* __restrict__ batch) {
    int i = blockIdx.x * 256 + threadIdx.x;
    if (i < N_NODES) atomicAdd(&g_cnt[batch[i]], 1.0f);
}
__global__ void k_zero_stats() {
    int i = blockIdx.x * 256 + threadIdx.x;
    if (i < N_GRAPHS * HID) { g_gsum[i] = 0.f; g_gsq[i] = 0.f; }
}

// Precompute M4 = We@W1 (4x256), c = be@W1 + b1, cvec = bio@W1b + hb1
__global__ void k_prep(const float* __restrict__ We, const float* __restrict__ be,
                       const float* __restrict__ W1, const float* __restrict__ b1,
                       const float* __restrict__ bio, const float* __restrict__ hW1,
                       const float* __restrict__ hb1) {
    int k = threadIdx.x;
    if (blockIdx.x == 0) {
        float c = b1[k];
        #pragma unroll 4
        for (int i = 0; i < HID; i++) c += be[i] * W1[i * HID + k];
        g_c[k] = c;
        #pragma unroll
        for (int j = 0; j < 4; j++) {
            float m = 0.f;
            #pragma unroll 4
            for (int i = 0; i < HID; i++) m += We[j * HID + i] * W1[i * HID + k];
            g_M4[j * HID + k] = m;
        }
    } else {
        float cv = hb1[k];
        #pragma unroll 4
        for (int i = 0; i < 512; i++) cv += bio[i] * hW1[(HID + i) * HID + k];
        g_cvec[k] = cv;
    }
}

__global__ void k_embed(const int* __restrict__ x, const float* __restrict__ embW) {
    int idx = blockIdx.x * 256 + threadIdx.x;
    if (idx >= N_NODES * 64) return;
    int node = idx >> 6, ch = idx & 63;
    ((float4*)g_h)[node * 64 + ch] = ((const float4*)embW)[x[node] * 64 + ch];
}

// ---------------- CSR-by-dst construction ----------------
__global__ void k_zero_misc() {
    int i = blockIdx.x * 256 + threadIdx.x;
    if (i < N_NODES) { g_deg[i] = 0; g_cur[i] = 0; }
}
__global__ void k_hist(const int* __restrict__ dst) {
    int e = blockIdx.x * 256 + threadIdx.x;
    if (e < N_EDGES) atomicAdd(&g_deg[dst[e]], 1);
}
__global__ void k_scan() {
    __shared__ int s[1024];
    __shared__ int off;
    int tid = threadIdx.x;
    if (tid == 0) off = 0;
    __syncthreads();
    for (int base = 0; base < N_NODES; base += 1024) {
        int v = (base + tid < N_NODES) ? g_deg[base + tid] : 0;
        s[tid] = v;
        __syncthreads();
        for (int d = 1; d < 1024; d <<= 1) {
            int t = (tid >= d) ? s[tid - d] : 0;
            __syncthreads();
            s[tid] += t;
            __syncthreads();
        }
        if (base + tid < N_NODES) g_rowptr[base + tid] = s[tid] - v + off;
        __syncthreads();
        if (tid == 0) off += s[1023];
        __syncthreads();
    }
}
__global__ void k_fill(const int* __restrict__ dst) {
    int e = blockIdx.x * 256 + threadIdx.x;
    if (e >= N_EDGES) return;
    int d = dst[e];
    int pos = g_rowptr[d] + atomicAdd(&g_cur[d], 1);
    g_perm[pos] = e;
}

// ---------------- aggregation ----------------
__global__ void k_agg(const int* __restrict__ src, const float* __restrict__ epsp) {
    __shared__ float s_eps;
    int n = blockIdx.x;
    int c = threadIdx.x;
    if (c == 0) s_eps = 1.0f + *epsp;
    __syncthreads();
    int start = g_rowptr[n];
    int deg = g_deg[n];
    float acc = s_eps * g_h[(size_t)n * HID + c];
    for (int i = 0; i < deg; i++) {
        int e = __ldg(&g_perm[start + i]);
        int s = __ldg(&src[e]);
        acc += fmaxf(g_h[(size_t)s * HID + c] + g_e[(size_t)e * HID + c], 0.f);
    }
    g_z[(size_t)n * HID + c] = acc;
}

// ====== fp32 SGEMM v6: R15 shape, inner loop on packed fma.rn.f32x2 ======
// C[M,256] = epilogue(A[M,256] @ B[256,256] + bias), B row-major [k][n] fp32.
// Block 64m x 128n; 8 warps; micro-tile 8m x 4n, acc as 8x2 packed f32x2 (u64).
// A frags warp-uniform broadcast LDS.64; B frags contiguous LDS.128 (as ulonglong2).
// KSTEP 16, 4-stage cp.async pipeline, 3 CTAs/SM.
// MODE 0: none. MODE 1: relu. MODE 2: A generated = relu(ea@M4+c); epilogue struct-scale.
#define BM 64
#define NSTAGE 4
#define SMK_BIAS 0           // 512 B
#define SMK_EA 512           // 1024 B (64 rows x float4)
#define SMK_M4 1536          // 4096 B
#define SMK_CS 5632          // 1024 B
#define SMK_ST 6656
#define SMK_STAGE 12288      // A 64x16x4 = 4096, B 16x128x4 = 8192
#define SMK_TOTAL (SMK_ST + NSTAGE * SMK_STAGE)  // 55808

template <int MODE>
__global__ void __launch_bounds__(256, 3) kg(const float* __restrict__ A,
                                             const float* __restrict__ B,
                                             const float* __restrict__ bias,
                                             float* __restrict__ C, int M,
                                             const float* __restrict__ ssp) {
    extern __shared__ char sm[];
    const uint32_t smb = smem_to_u32(sm);
    float* bias_s = (float*)(sm + SMK_BIAS);
    const float4* ea_s = (const float4*)(sm + SMK_EA);
    const float* M4s = (const float*)(sm + SMK_M4);
    const float* cs = (const float*)(sm + SMK_CS);

    const int tid = threadIdx.x;
    const int ty = tid >> 5;     // 0..7, rows ty*8..+7 (warp-uniform)
    const int tx = tid & 31;     // 0..31, cols tx*4..+3
    const int bm = blockIdx.x * BM, bn = blockIdx.y * 128;

    if (tid < 32) ((float4*)bias_s)[tid] = *((const float4*)(bias + bn) + tid);
    if (MODE == 2) {
        if (tid < BM) {
            int r = bm + tid;
            ((float4*)(sm + SMK_EA))[tid] =
                (r < M) ? ((const float4*)A)[r] : make_float4(0.f, 0.f, 0.f, 0.f);
        }
        ((float4*)(sm + SMK_M4))[tid] = ((const float4*)g_M4)[tid];
        ((float*)(sm + SMK_CS))[tid] = g_c[tid];
    }
    __syncthreads();

    // MODE2 generation state: thread covers row=tid>>2 (0..63), k-quad=(tid&3)*4
    const int grow_ = tid >> 2;
    const int gkq_ = (tid & 3) * 4;
    float4 eav = make_float4(0.f, 0.f, 0.f, 0.f);
    if (MODE == 2) eav = ea_s[grow_];

    auto prefetch = [&](int t) {
        const int s = t & (NSTAGE - 1);
        const int k0 = t * 16;
        const uint32_t stA = smb + SMK_ST + s * SMK_STAGE;
        const uint32_t stB = stA + 4096;
        if (MODE == 2) {
            float* ap = (float*)(sm + SMK_ST + s * SMK_STAGE) + grow_ * 16 + gkq_;
            #pragma unroll
            for (int q = 0; q < 4; q++) {
                int k = k0 + gkq_ + q;
                float v = cs[k] + eav.x * M4s[k] + eav.y * M4s[256 + k]
                        + eav.z * M4s[512 + k] + eav.w * M4s[768 + k];
                ap[q] = fmaxf(v, 0.f);
            }
        } else {
            int row = tid >> 2, seg = tid & 3;   // 64 rows x 4 segs
            int gr = bm + row;
            cp_async16(stA + (row * 16 + seg * 4) * 4,
                       A + (size_t)gr * HID + k0 + seg * 4, (gr < M) ? 16 : 0);
        }
        #pragma unroll
        for (int u = 0; u < 2; u++) {
            int idx = tid + u * 256;             // 0..511
            int brow = idx >> 5, bseg = idx & 31;
            cp_async16(stB + (brow * 128 + bseg * 4) * 4,
                       B + (size_t)(k0 + brow) * HID + bn + bseg * 4, 16);
        }
    };

    // packed accumulators: 8 rows x 2 (each u64 = 2 packed fp32 cols)
    unsigned long long acc[8][2];
    #pragma unroll
    for (int i = 0; i < 8; i++) {
        acc[i][0] = 0ULL;
        acc[i][1] = 0ULL;
    }

    prefetch(0); CP_COMMIT();
    prefetch(1); CP_COMMIT();
    prefetch(2); CP_COMMIT();

    for (int t = 0; t < 16; t++) {
        if (t + 3 < 16) {
            prefetch(t + 3);
            CP_COMMIT();
            CP_WAIT3();
        } else {
            CP_WAIT0();
        }
        __syncthreads();

        const float* Ast = (const float*)(sm + SMK_ST + (t & (NSTAGE - 1)) * SMK_STAGE);
        const float* Bst = Ast + 1024;

        #pragma unroll
        for (int kp = 0; kp < 8; kp++) {
            float2 av[8];
            #pragma unroll
            for (int i = 0; i < 8; i++)
                av[i] = *(const float2*)(Ast + (ty * 8 + i) * 16 + 2 * kp);
            ulonglong2 q0 = *(const ulonglong2*)(Bst + (2 * kp) * 128 + tx * 4);
            ulonglong2 q1 = *(const ulonglong2*)(Bst + (2 * kp + 1) * 128 + tx * 4);
            #pragma unroll
            for (int i = 0; i < 8; i++) {
                unsigned long long a2;
                unsigned ax = __float_as_uint(av[i].x);
                asm("mov.b64 %0, {%1, %1};" : "=l"(a2) : "r"(ax));
                asm("fma.rn.f32x2 %0, %1, %2, %0;" : "+l"(acc[i][0]) : "l"(a2), "l"(q0.x));
                asm("fma.rn.f32x2 %0, %1, %2, %0;" : "+l"(acc[i][1]) : "l"(a2), "l"(q0.y));
            }
            #pragma unroll
            for (int i = 0; i < 8; i++) {
                unsigned long long a2;
                unsigned ay = __float_as_uint(av[i].y);
                asm("mov.b64 %0, {%1, %1};" : "=l"(a2) : "r"(ay));
                asm("fma.rn.f32x2 %0, %1, %2, %0;" : "+l"(acc[i][0]) : "l"(a2), "l"(q1.x));
                asm("fma.rn.f32x2 %0, %1, %2, %0;" : "+l"(acc[i][1]) : "l"(a2), "l"(q1.y));
            }
        }
        __syncthreads();
    }

    // ---- epilogue ----
    float ss = 1.f;
    if (MODE == 2) ss = *ssp;
    float4 bv = ((const float4*)bias_s)[tx];

    #pragma unroll
    for (int i = 0; i < 8; i++) {
        int lr = ty * 8 + i;
        int r = bm + lr;
        if (r < M) {
            float f = 1.f;
            if (MODE == 2) f = (ea_s[lr].y > 0.f) ? ss : 1.f;
            float2 p0 = *(float2*)&acc[i][0];
            float2 p1 = *(float2*)&acc[i][1];
            float4 o;
            o.x = p0.x + bv.x;
            o.y = p0.y + bv.y;
            o.z = p1.x + bv.z;
            o.w = p1.y + bv.w;
            if (MODE == 1) {
                o.x = fmaxf(o.x, 0.f); o.y = fmaxf(o.y, 0.f);
                o.z = fmaxf(o.z, 0.f); o.w = fmaxf(o.w, 0.f);
            }
            if (MODE == 2) { o.x *= f; o.y *= f; o.z *= f; o.w *= f; }
            *(float4*)(C + (size_t)r * HID + bn + tx * 4) = o;
        }
    }
}

// ---------------- fused per-graph stats ----------------
#define STRIP 64
__global__ void k_stats(const float* __restrict__ h, const int* __restrict__ batch) {
    __shared__ int bs[STRIP];
    int c = threadIdx.x;
    int n0 = blockIdx.x * STRIP;
    int n1 = min(n0 + STRIP, N_NODES);
    if (c < STRIP && n0 + c < N_NODES) bs[c] = batch[n0 + c];
    __syncthreads();
    float as = 0.f, aq = 0.f;
    int cur = bs[0];
    for (int n = n0; n < n1; n++) {
        int b = bs[n - n0];
        if (b != cur) {
            atomicAdd(&g_gsum[cur * HID + c], as);
            atomicAdd(&g_gsq[cur * HID + c], aq);
            as = 0.f; aq = 0.f;
            cur = b;
        }
        float v = h[(size_t)n * HID + c];
        as += v;
        aq += v * v;
    }
    atomicAdd(&g_gsum[cur * HID + c], as);
    atomicAdd(&g_gsq[cur * HID + c], aq);
}

__global__ void k_norm2(const int* __restrict__ batch, const float* __restrict__ gamma,
                        const float* __restrict__ beta, const float* __restrict__ alpha) {
    int idx = blockIdx.x * 256 + threadIdx.x;
    if (idx >= N_NODES * HID) return;
    int node = idx >> 8, c = idx & 255;
    int b = batch[node];
    float a = alpha[c];
    float inv = 1.f / fmaxf(g_cnt[b], 1.f);
    float mean = g_gsum[b * HID + c] * inv;
    float msq = g_gsq[b * HID + c] * inv;
    float var = msq - (2.f * a - a * a) * mean * mean;
    float hc = g_h[idx] - a * mean;
    g_h[idx] = gamma[c] * hc * rsqrtf(var + EPSN) + beta[c];
}

// ---------------- head ----------------
__global__ void k_head(const float* __restrict__ headW1, const float* __restrict__ headW2,
                       const float* __restrict__ headb2, float* __restrict__ out) {
    int g = blockIdx.x;
    int j = threadIdx.x;
    __shared__ float gs[HID];
    __shared__ float red[HID];
    float inv = 1.f / fmaxf(g_cnt[g], 1.f);
    gs[j] = g_gsum[g * HID + j] * inv;
    __syncthreads();
    float acc = g_cvec[j];
    #pragma unroll 8
    for (int k = 0; k < HID; k++) acc += gs[k] * headW1[k * HID + j];
    acc = fmaxf(acc, 0.f);
    red[j] = acc * headW2[j];
    __syncthreads();
    for (int s = 128; s > 0; s >>= 1) {
        if (j < s) red[j] += red[j + s];
        __syncthreads();
    }
    if (j == 0) out[g] = red[0] + headb2[0];
}

// ---------------- launcher ----------------
extern "C" void kernel_launch(void* const* d_in, const int* in_sizes, int n_in,
                              void* d_out, int out_size) {
    const int* x = (const int*)d_in[0];
    const int* edge_index = (const int*)d_in[1];
    const float* edge_attr = (const float*)d_in[2];
    const int* batch = (const int*)d_in[3];
    const float* node_emb_W = (const float*)d_in[4];
    const float* edge_emb_W = (const float*)d_in[5];
    const float* edge_emb_b = (const float*)d_in[6];
    const float* edge_mlp_W1 = (const float*)d_in[7];
    const float* edge_mlp_b1 = (const float*)d_in[8];
    const float* edge_mlp_W2 = (const float*)d_in[9];
    const float* edge_mlp_b2 = (const float*)d_in[10];
    const float* struct_scale = (const float*)d_in[11];
    const float* conv_W1 = (const float*)d_in[12];
    const float* conv_b1 = (const float*)d_in[13];
    const float* conv_W2 = (const float*)d_in[14];
    const float* conv_b2 = (const float*)d_in[15];
    const float* conv_eps = (const float*)d_in[16];
    const float* norm_gamma = (const float*)d_in[17];
    const float* norm_beta = (const float*)d_in[18];
    const float* norm_alpha = (const float*)d_in[19];
    const float* head_W1 = (const float*)d_in[21];
    const float* head_W2 = (const float*)d_in[23];
    const float* head_b2 = (const float*)d_in[24];
    float* out = (float*)d_out;

    const int* src = edge_index;
    const int* dst = edge_index + N_EDGES;

    cudaFuncSetAttribute(kg<0>, cudaFuncAttributeMaxDynamicSharedMemorySize, SMK_TOTAL);
    cudaFuncSetAttribute(kg<1>, cudaFuncAttributeMaxDynamicSharedMemorySize, SMK_TOTAL);
    cudaFuncSetAttribute(kg<2>, cudaFuncAttributeMaxDynamicSharedMemorySize, SMK_TOTAL);

    // launches 1-3
    k_zero_cnt<<<1, 256>>>();
    k_count<<<(N_NODES + 255) / 256, 256>>>(batch);
    k_prep<<<2, 256>>>(edge_emb_W, edge_emb_b, edge_mlp_W1, edge_mlp_b1,
                       (const float*)d_in[20], head_W1, (const float*)d_in[22]);

    // launch 4 (profiled slot): edge GEMM
    kg<2><<<dim3(N_EDGES / BM, 2), 256, SMK_TOTAL>>>(edge_attr, edge_mlp_W2,
                                                     edge_mlp_b2, g_e, N_EDGES,
                                                     struct_scale);

    k_embed<<<(N_NODES * 64 + 255) / 256, 256>>>(x, node_emb_W);

    // CSR-by-dst build
    k_zero_misc<<<(N_NODES + 255) / 256, 256>>>();
    k_hist<<<(N_EDGES + 255) / 256, 256>>>(dst);
    k_scan<<<1, 1024>>>();
    k_fill<<<(N_EDGES + 255) / 256, 256>>>(dst);

    const int gemm_mx = (N_NODES + BM - 1) / BM;
    for (int l = 0; l < LAYERS; l++) {
        k_agg<<<N_NODES, 256>>>(src, conv_eps + l);
        kg<1><<<dim3(gemm_mx, 2), 256, SMK_TOTAL>>>(g_z, conv_W1 + (size_t)l * HID * HID,
                                                    conv_b1 + l * HID, g_t, N_NODES, nullptr);
        kg<0><<<dim3(gemm_mx, 2), 256, SMK_TOTAL>>>(g_t, conv_W2 + (size_t)l * HID * HID,
                                                    conv_b2 + l * HID, g_h, N_NODES, nullptr);
        k_zero_stats<<<(N_GRAPHS * HID + 255) / 256, 256>>>();
        k_stats<<<(N_NODES + STRIP - 1) / STRIP, 256>>>(g_h, batch);
        k_norm2<<<(N_NODES * HID + 255) / 256, 256>>>(batch, norm_gamma + l * HID,
                                                      norm_beta + l * HID, norm_alpha + l * HID);
    }

    // pool + head
    k_zero_stats<<<(N_GRAPHS * HID + 255) / 256, 256>>>();
    k_stats<<<(N_NODES + STRIP - 1) / STRIP, 256>>>(g_h, batch);
    k_head<<<N_GRAPHS, 256>>>(head_W1, head_W2, head_b2, out);
}